// round 4
// baseline (speedup 1.0000x reference)
#include <cuda_runtime.h>

// ---------------- problem constants ----------------
#define KB     8
#define KC     64
#define KHW    76800      // 240*320
#define KCL    10
#define ALPHA_C   0.02f
#define DELTA_C   0.5f
#define MINW_C    50.0f

// pass-1 tiling: (b, chunk, cgrp) -> 960 blocks of 1280 pixels, 32 channels
#define CHUNKS1 60
#define PX1     (KHW / CHUNKS1)   // 1280
#define NBLK1   (KB * CHUNKS1 * 2)

// pass-2 tiling: 600 blocks of 1024 pixels (128 thr * 8 px)
#define CHUNKS3 75
#define PX3     (KHW / CHUNKS3)   // 1024
#define NBLK3   (KB * CHUNKS3)    // 600

// ---------------- device scratch (zero-init .bss; each launch restores) ----
__device__ float g_sums[KB][KC][KCL];     // K1 accumulates; K2 zeroes
__device__ float g_cnt[KB][KCL];          // K1 accumulates; K2 zeroes
__device__ float g_means[KB][KCL][KC];    // K2 overwrites
__device__ float g_d2[KB * KCL];          // K3 accumulates; finalize zeroes
__device__ float g_nk[KB * KCL];          // K3 accumulates; finalize zeroes
__device__ unsigned int g_tick;           // ticket; finalize zeroes

// ---------------- f32x2 helpers ----------------
__device__ __forceinline__ unsigned long long pack2(float lo, float hi) {
    unsigned long long r;
    asm("mov.b64 %0, {%1, %2};" : "=l"(r) : "f"(lo), "f"(hi));
    return r;
}
__device__ __forceinline__ void unpack2(unsigned long long v, float& lo, float& hi) {
    asm("mov.b64 {%0, %1}, %2;" : "=f"(lo), "=f"(hi) : "l"(v));
}
__device__ __forceinline__ void ffma2(unsigned long long& d,
                                      unsigned long long a, unsigned long long b) {
    asm("fma.rn.f32x2 %0, %1, %2, %0;" : "+l"(d) : "l"(a), "l"(b));
}

// =====================================================================
// K1: per-cluster channel sums + counts.
// 8 warps/block; warp owns a 4-channel slab (block covers 32 channels,
// 2 channel-groups per chunk). acc = 40 regs -> 4 blocks/SM target.
// =====================================================================
__global__ __launch_bounds__(256, 4) void k1_sums(const float* __restrict__ x,
                                                  const int* __restrict__ cmask)
{
    __shared__ unsigned char s_cm[PX1];
    __shared__ int s_cnt[KCL];

    const int bid   = blockIdx.x;
    const int b     = bid / (CHUNKS1 * 2);
    const int r0    = bid % (CHUNKS1 * 2);
    const int cgrp  = r0 & 1;
    const int pbase = (r0 >> 1) * PX1;
    const int tid   = threadIdx.x;
    const int lane  = tid & 31;
    const int warp  = tid >> 5;

    if (tid < KCL) s_cnt[tid] = 0;

    // stage masks (+ counts only from channel-group 0)
    const int* cmb = cmask + b * KHW + pbase;
    if (cgrp == 0) {
        int cnt[KCL];
#pragma unroll
        for (int k = 0; k < KCL; k++) cnt[k] = 0;
#pragma unroll
        for (int i = 0; i < PX1 / 256; i++) {
            const int p = tid + i * 256;
            const int v = cmb[p];
            s_cm[p] = (unsigned char)v;
#pragma unroll
            for (int k = 0; k < KCL; k++) cnt[k] += (v == k);
        }
        __syncthreads();
#pragma unroll
        for (int k = 0; k < KCL; k++) {
            int v = cnt[k];
#pragma unroll
            for (int o = 16; o; o >>= 1) v += __shfl_xor_sync(0xffffffffu, v, o);
            if (lane == 0) atomicAdd(&s_cnt[k], v);
        }
        __syncthreads();
        if (tid < KCL) atomicAdd(&g_cnt[b][tid], (float)s_cnt[tid]);
    } else {
#pragma unroll
        for (int i = 0; i < PX1 / 256; i++) {
            const int p = tid + i * 256;
            s_cm[p] = (unsigned char)cmb[p];
        }
        __syncthreads();
    }

    // main accumulation: warp's 4 channels
    const int c0 = cgrp * 32 + warp * 4;
    const float* xp = x + ((size_t)(b * KC + c0)) * KHW + pbase;

    unsigned long long acc[4][5];
#pragma unroll
    for (int j = 0; j < 4; j++)
#pragma unroll
        for (int kk = 0; kk < 5; kk++) acc[j][kk] = 0ull;

#pragma unroll 2
    for (int p = lane; p < PX1; p += 32) {
        const int cmv = s_cm[p];
        unsigned long long m2[5];
#pragma unroll
        for (int kk = 0; kk < 5; kk++) {
            const float lo = (cmv == 2 * kk)     ? 1.0f : 0.0f;
            const float hi = (cmv == 2 * kk + 1) ? 1.0f : 0.0f;
            m2[kk] = pack2(lo, hi);
        }
#pragma unroll
        for (int j = 0; j < 4; j++) {
            const float xv = xp[(size_t)j * KHW + p];
            const unsigned long long xx = pack2(xv, xv);
#pragma unroll
            for (int kk = 0; kk < 5; kk++) ffma2(acc[j][kk], xx, m2[kk]);
        }
    }

    // warp butterfly reduce, lane0 atomics into global sums
#pragma unroll
    for (int j = 0; j < 4; j++) {
#pragma unroll
        for (int kk = 0; kk < 5; kk++) {
            float lo, hi;
            unpack2(acc[j][kk], lo, hi);
#pragma unroll
            for (int o = 16; o; o >>= 1) {
                lo += __shfl_xor_sync(0xffffffffu, lo, o);
                hi += __shfl_xor_sync(0xffffffffu, hi, o);
            }
            if (lane == 0) {
                atomicAdd(&g_sums[b][c0 + j][2 * kk],     lo);
                atomicAdd(&g_sums[b][c0 + j][2 * kk + 1], hi);
            }
        }
    }
}

// =====================================================================
// K2: normalize means; zero accumulators for next launch.
// =====================================================================
__global__ __launch_bounds__(64) void k2_means()
{
    const int b = blockIdx.x / KCL;
    const int k = blockIdx.x % KCL;
    const int c = threadIdx.x;
    __shared__ float s_sq[2];

    const float cntv = g_cnt[b][k];
    const float sv   = g_sums[b][c][k];
    const float mean = sv / (cntv + 1e-10f);

    float sq = mean * mean;
#pragma unroll
    for (int o = 16; o; o >>= 1) sq += __shfl_xor_sync(0xffffffffu, sq, o);
    if ((c & 31) == 0) s_sq[c >> 5] = sq;
    __syncthreads();

    const float inv = 1.0f / fmaxf(sqrtf(s_sq[0] + s_sq[1]), 1e-12f);
    g_means[b][k][c] = mean * inv;

    __syncthreads();
    g_sums[b][c][k] = 0.0f;
    if (c == 0) g_cnt[b][k] = 0.0f;
}

// =====================================================================
// K3: second pass, 8 px/thread (2x float4), 128-thread blocks,
// padded-smem means, shared bins, ticket-last-block finalize.
// =====================================================================
__global__ __launch_bounds__(128) void k3_intra(const float* __restrict__ x,
                                                const int* __restrict__ cmask,
                                                float* __restrict__ out)
{
    __shared__ float msh[KCL * 65];
    __shared__ float s_d2[KCL];
    __shared__ float s_nk[KCL];
    __shared__ unsigned int s_last;

    const int bid   = blockIdx.x;
    const int b     = bid / CHUNKS3;
    const int pbase = (bid % CHUNKS3) * PX3;
    const int tid   = threadIdx.x;
    const int lane  = tid & 31;
    const int warp  = tid >> 5;

#pragma unroll
    for (int i = 0; i < 5; i++) {
        const int idx = tid + i * 128;
        msh[(idx >> 6) * 65 + (idx & 63)] = ((const float*)g_means)[b * KCL * KC + idx];
    }
    if (tid < KCL) { s_d2[tid] = 0.f; s_nk[tid] = 0.f; }
    __syncthreads();

    const int p0 = pbase + tid * 8;
    const int4 cma = *(const int4*)(cmask + b * KHW + p0);
    const int4 cmb4 = *(const int4*)(cmask + b * KHW + p0 + 4);
    const float* xb = x + (size_t)b * KC * KHW + p0;

    const int kk8[8] = { cma.x, cma.y, cma.z, cma.w, cmb4.x, cmb4.y, cmb4.z, cmb4.w };
    const float* mp[8];
#pragma unroll
    for (int i = 0; i < 8; i++) mp[i] = &msh[kk8[i] * 65];

    float d[8];
#pragma unroll
    for (int i = 0; i < 8; i++) d[i] = 0.f;

#pragma unroll 8
    for (int c = 0; c < KC; c++) {
        const float4 xa = *(const float4*)(xb + (size_t)c * KHW);
        const float4 xc = *(const float4*)(xb + (size_t)c * KHW + 4);
        d[0] = fmaf(xa.x, mp[0][c], d[0]);
        d[1] = fmaf(xa.y, mp[1][c], d[1]);
        d[2] = fmaf(xa.z, mp[2][c], d[2]);
        d[3] = fmaf(xa.w, mp[3][c], d[3]);
        d[4] = fmaf(xc.x, mp[4][c], d[4]);
        d[5] = fmaf(xc.y, mp[5][c], d[5]);
        d[6] = fmaf(xc.z, mp[6][c], d[6]);
        d[7] = fmaf(xc.w, mp[7][c], d[7]);
    }

#pragma unroll
    for (int i = 0; i < 8; i++) {
        const float dd = 0.5f * (1.0f - d[i]);
        atomicAdd(&s_d2[kk8[i]], dd * dd);
        if (dd > ALPHA_C) atomicAdd(&s_nk[kk8[i]], 1.0f);
    }
    __syncthreads();
    if (tid < KCL) {
        atomicAdd(&g_d2[b * KCL + tid], s_d2[tid]);
        atomicAdd(&g_nk[b * KCL + tid], s_nk[tid]);
    }

    // ---- ticket: last block finalizes ----
    __threadfence();
    __syncthreads();
    if (tid == 0)
        s_last = (atomicAdd(&g_tick, 1u) == (unsigned)(NBLK3 - 1)) ? 1u : 0u;
    __syncthreads();
    if (!s_last) return;
    __threadfence();

    // ---------- finalize (one block, 128 threads / 4 warps) ----------
    __shared__ float fmsh[KB * KCL * 65];

    for (int i = tid; i < KB * KCL * KC; i += 128)
        fmsh[(i >> 6) * 65 + (i & 63)] = ((const float*)g_means)[i];
    __syncthreads();

    // inter loss: warp-per-ordered-pair (720 pairs / 4 warps), lane0 accumulates
    float acc_inter = 0.f;
    for (int pr = warp; pr < KB * KCL * (KCL - 1); pr += 4) {
        const int bb = pr / 90;
        const int r  = pr % 90;
        const int k  = r / 9;
        int l = r % 9; if (l >= k) l++;
        const float* mk = &fmsh[(bb * KCL + k) * 65];
        const float* ml = &fmsh[(bb * KCL + l) * 65];
        float dv = mk[lane] * ml[lane] + mk[lane + 32] * ml[lane + 32];
#pragma unroll
        for (int o = 16; o; o >>= 1) dv += __shfl_xor_sync(0xffffffffu, dv, o);
        const float h = fmaxf(DELTA_C - 0.5f * (1.0f - dv), 0.0f);
        if (lane == 0) acc_inter += h * h;
    }

    // intra finalize + resets
    float acc_intra = 0.f, acc_ind = 0.f;
    if (tid < KB * KCL) {
        const float nk = g_nk[tid];
        acc_intra = g_d2[tid] / (fmaxf(nk, MINW_C) * (float)KCL);
        acc_ind   = nk;
        g_nk[tid] = 0.f;
        g_d2[tid] = 0.f;
    }

    float v0 = acc_inter, v1 = acc_intra, v2 = acc_ind;
#pragma unroll
    for (int o = 16; o; o >>= 1) {
        v0 += __shfl_xor_sync(0xffffffffu, v0, o);
        v1 += __shfl_xor_sync(0xffffffffu, v1, o);
        v2 += __shfl_xor_sync(0xffffffffu, v2, o);
    }
    __shared__ float s_r0[4], s_r1[4], s_r2[4];
    if (lane == 0) { s_r0[warp] = v0; s_r1[warp] = v1; s_r2[warp] = v2; }
    __syncthreads();
    if (tid == 0) {
        float t0 = 0.f, t1 = 0.f, t2 = 0.f;
#pragma unroll
        for (int w = 0; w < 4; w++) { t0 += s_r0[w]; t1 += s_r1[w]; t2 += s_r2[w]; }
        const float inter_loss = t0 / ((float)(KCL * (KCL - 1) / 2) * (float)KB);
        const float intra_loss = (t2 > 0.f) ? (t1 / (float)KB) : 0.f;
        out[0] = intra_loss + inter_loss;
        out[1] = intra_loss;
        out[2] = inter_loss;
        g_tick = 0u;
    }
}

// =====================================================================
extern "C" void kernel_launch(void* const* d_in, const int* in_sizes, int n_in,
                              void* d_out, int out_size)
{
    const float* x   = (const float*)d_in[0];
    const int*   cm  = (const int*)d_in[1];
    float*       out = (float*)d_out;

    k1_sums<<<NBLK1, 256>>>(x, cm);
    k2_means<<<KB * KCL, 64>>>();
    k3_intra<<<NBLK3, 128>>>(x, cm, out);
}